// round 2
// baseline (speedup 1.0000x reference)
#include <cuda_runtime.h>
#include <math.h>
#include <stdint.h>

#define N 4096
#define M 4096
#define D 512

#define BN 32
#define BM 128
#define KT 16

typedef unsigned long long u64;

// scratch (no device allocation allowed)
__device__ __align__(16) float g_x2[N];
__device__ __align__(16) float g_y2[M];
__device__ __align__(16) float g_m[N];
__device__ __align__(16) float g_s[N];
__device__ __align__(16) float g_nll[N];
__device__ int g_is64;

// ---------------- packed f32x2 helpers ----------------
__device__ __forceinline__ u64 pack2(float x, float y) {
    u64 r;
    asm("mov.b64 %0, {%1, %2};" : "=l"(r) : "f"(x), "f"(y));
    return r;
}
__device__ __forceinline__ void unpack2(u64 v, float& x, float& y) {
    asm("mov.b64 {%0, %1}, %2;" : "=f"(x), "=f"(y) : "l"(v));
}
__device__ __forceinline__ void fma2(u64& d, u64 a, u64 b) {
    asm("fma.rn.f32x2 %0, %1, %2, %3;" : "=l"(d) : "l"(a), "l"(b), "l"(d));
}

// ---------------- kernel 0: detect label width ----------------
// int64 little-endian labels < 4096 => all odd 32-bit words are 0.
// int32 labels => odd words are real labels; all-zero has ~0 probability.
__global__ void detect_labels_kernel(const unsigned int* __restrict__ w) {
    __shared__ int any;
    if (threadIdx.x == 0) any = 0;
    __syncthreads();
    for (int i = 1 + 2 * threadIdx.x; i < 4096; i += 2 * blockDim.x)
        if (w[i] != 0u) any = 1;   // benign race: only writes 1
    __syncthreads();
    if (threadIdx.x == 0) g_is64 = (any == 0) ? 1 : 0;
}

// ---------------- kernel 1: row squared norms ----------------
__global__ void norms_kernel(const float* __restrict__ feat,
                             const float* __restrict__ feat2) {
    int wid  = (blockIdx.x * blockDim.x + threadIdx.x) >> 5;
    int lane = threadIdx.x & 31;
    if (wid >= N + M) return;
    const float* src = (wid < N) ? feat + (size_t)wid * D
                                 : feat2 + (size_t)(wid - N) * D;
    float s = 0.f;
#pragma unroll
    for (int j = 0; j < 4; j++) {
        float4 v = ((const float4*)src)[lane + 32 * j];
        s += v.x * v.x + v.y * v.y + v.z * v.z + v.w * v.w;
    }
#pragma unroll
    for (int off = 16; off; off >>= 1) s += __shfl_xor_sync(0xffffffffu, s, off);
    if (lane == 0) {
        if (wid < N) g_x2[wid] = s;
        else         g_y2[wid - N] = s;
    }
}

// ---------------- kernel 2: fused GEMM + online softmax ----------------
// grid = N/BN = 128 blocks, 256 threads. Block owns rows [r0, r0+32), all M cols.
// warp w owns rows r0+4w .. r0+4w+3 ; lane owns cols c0+4*lane .. +3 per tile.
__global__ __launch_bounds__(256, 1)
void main_kernel(const float* __restrict__ feat,
                 const float* __restrict__ feat2,
                 const float* __restrict__ temp) {
    __shared__ __align__(16) float As[KT][BN + 4];    // [k][row], padded
    __shared__ __align__(16) float Bs[KT][BM + 4];    // [k][col], padded (stride 132)

    const int tid  = threadIdx.x;
    const int warp = tid >> 5;
    const int lane = tid & 31;
    const int r0   = blockIdx.x * BN;

    const float invT = 1.0f / temp[0];

    float x2r[4];
#pragma unroll
    for (int i = 0; i < 4; i++) x2r[i] = g_x2[r0 + 4 * warp + i];

    float rm[4], rs[4];
#pragma unroll
    for (int i = 0; i < 4; i++) { rm[i] = -INFINITY; rs[i] = 0.f; }

    for (int ct = 0; ct < M / BM; ct++) {
        const int c0 = ct * BM;
        // acc packed over row-pairs: accp[j][p] holds rows (4w+2p, 4w+2p+1), col 4*lane+j
        u64 accp[4][2];
#pragma unroll
        for (int j = 0; j < 4; j++) { accp[j][0] = 0ull; accp[j][1] = 0ull; }

        for (int kt = 0; kt < D / KT; kt++) {
            const int k0 = kt * KT;
            // stage A tile: 32 rows x 16 k = 128 float4 ; threads < 128
            if (tid < 128) {
                int kv  = tid & 3;          // 0..3 (float4 index along k)
                int row = tid >> 2;         // 0..31
                float4 a = *(const float4*)(feat + (size_t)(r0 + row) * D + k0 + kv * 4);
                As[kv * 4 + 0][row] = a.x;
                As[kv * 4 + 1][row] = a.y;
                As[kv * 4 + 2][row] = a.z;
                As[kv * 4 + 3][row] = a.w;
            }
            // stage B tile: 128 cols x 16 k = 512 float4 ; 2 per thread
            {
                int kv   = tid & 3;         // 0..3
                int colb = tid >> 2;        // 0..63
#pragma unroll
                for (int u = 0; u < 2; u++) {
                    int col = colb + 64 * u;
                    float4 b = *(const float4*)(feat2 + (size_t)(c0 + col) * D + k0 + kv * 4);
                    Bs[kv * 4 + 0][col] = b.x;
                    Bs[kv * 4 + 1][col] = b.y;
                    Bs[kv * 4 + 2][col] = b.z;
                    Bs[kv * 4 + 3][col] = b.w;
                }
            }
            __syncthreads();
#pragma unroll
            for (int kk = 0; kk < KT; kk++) {
                u64 a01 = *(const u64*)&As[kk][4 * warp];
                u64 a23 = *(const u64*)&As[kk][4 * warp + 2];
                float4 b = *(const float4*)&Bs[kk][4 * lane];
                u64 b0 = pack2(b.x, b.x);
                u64 b1 = pack2(b.y, b.y);
                u64 b2 = pack2(b.z, b.z);
                u64 b3 = pack2(b.w, b.w);
                fma2(accp[0][0], a01, b0); fma2(accp[0][1], a23, b0);
                fma2(accp[1][0], a01, b1); fma2(accp[1][1], a23, b1);
                fma2(accp[2][0], a01, b2); fma2(accp[2][1], a23, b2);
                fma2(accp[3][0], a01, b3); fma2(accp[3][1], a23, b3);
            }
            __syncthreads();
        }

        // ---- epilogue: distances + online softmax update ----
        float acc[4][4];
#pragma unroll
        for (int j = 0; j < 4; j++) {
            unpack2(accp[j][0], acc[0][j], acc[1][j]);
            unpack2(accp[j][1], acc[2][j], acc[3][j]);
        }
        float4 y4 = *(const float4*)(g_y2 + c0 + 4 * lane);
        float yv[4] = { y4.x, y4.y, y4.z, y4.w };
#pragma unroll
        for (int i = 0; i < 4; i++) {
            float lg[4];
#pragma unroll
            for (int j = 0; j < 4; j++) {
                float d2 = fmaxf(x2r[i] + yv[j] - 2.0f * acc[i][j], 0.0f);
                lg[j] = -sqrtf(d2) * invT;
            }
            float tm = fmaxf(fmaxf(lg[0], lg[1]), fmaxf(lg[2], lg[3]));
            float nm = fmaxf(rm[i], tm);
            float s  = rs[i] * __expf(rm[i] - nm);
#pragma unroll
            for (int j = 0; j < 4; j++) s += __expf(lg[j] - nm);
            rm[i] = nm;
            rs[i] = s;
        }
    }

    // ---- warp-combine (lanes hold disjoint column subsets of same 4 rows) ----
#pragma unroll
    for (int i = 0; i < 4; i++) {
        float m = rm[i], s = rs[i];
#pragma unroll
        for (int off = 16; off; off >>= 1) {
            float om = __shfl_xor_sync(0xffffffffu, m, off);
            float os = __shfl_xor_sync(0xffffffffu, s, off);
            float nm = fmaxf(m, om);
            s = s * __expf(m - nm) + os * __expf(om - nm);
            m = nm;
        }
        if (lane == 0) {
            g_m[r0 + 4 * warp + i] = m;
            g_s[r0 + 4 * warp + i] = s;
        }
    }
}

// ---------------- kernel 3: per-row finalize (label distance + nll) ----------------
__global__ void finalize_kernel(const float* __restrict__ feat,
                                const float* __restrict__ feat2,
                                const void* __restrict__ labels,
                                const float* __restrict__ temp) {
    int wid  = (blockIdx.x * blockDim.x + threadIdx.x) >> 5;
    int lane = threadIdx.x & 31;
    if (wid >= N) return;
    long long l;
    if (g_is64) l = ((const long long*)labels)[wid];
    else        l = (long long)((const int*)labels)[wid];
    // defensive clamp: a wrong label shows as rel_err, not a crash
    if (l < 0) l = 0;
    if (l >= M) l = M - 1;
    const float* a = feat  + (size_t)wid * D;
    const float* b = feat2 + (size_t)l * D;
    float dot = 0.f;
#pragma unroll
    for (int j = 0; j < 4; j++) {
        float4 av = ((const float4*)a)[lane + 32 * j];
        float4 bv = ((const float4*)b)[lane + 32 * j];
        dot += av.x * bv.x + av.y * bv.y + av.z * bv.z + av.w * bv.w;
    }
#pragma unroll
    for (int off = 16; off; off >>= 1) dot += __shfl_xor_sync(0xffffffffu, dot, off);
    if (lane == 0) {
        float d2   = fmaxf(g_x2[wid] + g_y2[l] - 2.0f * dot, 0.0f);
        float dist = sqrtf(d2);
        float invT = 1.0f / temp[0];
        // nll = -(logit_label - lse) = dist/T + m + log(s)
        g_nll[wid] = dist * invT + g_m[wid] + logf(g_s[wid]);
    }
}

// ---------------- kernel 4: deterministic mean reduction ----------------
__global__ void reduce_kernel(float* __restrict__ out) {
    __shared__ float sh[256];
    int tid = threadIdx.x;
    float s = 0.f;
    for (int i = tid; i < N; i += 256) s += g_nll[i];
    sh[tid] = s;
    __syncthreads();
    for (int off = 128; off; off >>= 1) {
        if (tid < off) sh[tid] += sh[tid + off];
        __syncthreads();
    }
    if (tid == 0) out[0] = sh[0] / (float)N;
}

// ---------------- launch ----------------
extern "C" void kernel_launch(void* const* d_in, const int* in_sizes, int n_in,
                              void* d_out, int out_size) {
    const float* feat   = (const float*)d_in[0];
    const float* feat2  = (const float*)d_in[1];
    const void*  labels = d_in[2];
    const float* temp   = (const float*)d_in[3];
    float* out = (float*)d_out;

    detect_labels_kernel<<<1, 256>>>((const unsigned int*)labels);
    norms_kernel<<<(N + M) / 8, 256>>>(feat, feat2);            // 8192 warps
    main_kernel<<<N / BN, 256>>>(feat, feat2, temp);            // 128 blocks
    finalize_kernel<<<N / 8, 256>>>(feat, feat2, labels, temp); // 4096 warps
    reduce_kernel<<<1, 256>>>(out);
}

// round 4
// speedup vs baseline: 6.0009x; 6.0009x over previous
#include <cuda_runtime.h>
#include <math.h>
#include <stdint.h>

#define N 4096
#define M 4096
#define D 512

#define BT 128          // CTA tile (rows and cols)
#define KC 16           // K per pipeline stage
#define NSTG 4
#define ITERS (D / KC)  // 32
#define STRD 20         // smem row stride in floats (bank-conflict-free, 80B = 5x16B)
#define STAGE_WORDS (2 * BT * STRD)           // A + B
#define STAGE_BYTES (STAGE_WORDS * 4)         // 20480
#define SMEM_DYN (NSTG * STAGE_BYTES)         // 81920

typedef unsigned long long u64;

// scratch
__device__ __align__(16) uint32_t g_at[N * D];   // feat  in tf32 (rna)
__device__ __align__(16) uint32_t g_bt[M * D];   // feat2 in tf32 (rna)
__device__ __align__(16) float g_x2[N];
__device__ __align__(16) float g_y2[M];
__device__ __align__(16) float g_part[M / BT][N];   // [32][4096] col-chunk partial expsums
__device__ __align__(16) float g_dlbl[N];
__device__ __align__(16) float g_nll[N];
__device__ int g_is64;

// ---------------- helpers ----------------
__device__ __forceinline__ void cp16(void* dst, const void* src) {
    uint32_t d;
    asm("{ .reg .u64 t; cvta.to.shared.u64 t, %1; cvt.u32.u64 %0, t; }" : "=r"(d) : "l"(dst));
    asm volatile("cp.async.cg.shared.global [%0], [%1], 16;" :: "r"(d), "l"(src) : "memory");
}
__device__ __forceinline__ void cp_commit() { asm volatile("cp.async.commit_group;" ::: "memory"); }
__device__ __forceinline__ void cp_wait2()  { asm volatile("cp.async.wait_group 2;"  ::: "memory"); }
__device__ __forceinline__ uint32_t to_tf32(float x) {
    uint32_t r; asm("cvt.rna.tf32.f32 %0, %1;" : "=r"(r) : "f"(x)); return r;
}
__device__ __forceinline__ float sqa(float x)  { float r; asm("sqrt.approx.f32 %0, %1;" : "=f"(r) : "f"(x)); return r; }
__device__ __forceinline__ float ex2a(float x) { float r; asm("ex2.approx.f32 %0, %1;"  : "=f"(r) : "f"(x)); return r; }

__device__ __forceinline__ void mma8(float* c, const uint32_t* a, const uint32_t* b) {
    asm volatile(
        "mma.sync.aligned.m16n8k8.row.col.f32.tf32.tf32.f32 "
        "{%0,%1,%2,%3}, {%4,%5,%6,%7}, {%8,%9}, {%0,%1,%2,%3};"
        : "+f"(c[0]), "+f"(c[1]), "+f"(c[2]), "+f"(c[3])
        : "r"(a[0]), "r"(a[1]), "r"(a[2]), "r"(a[3]), "r"(b[0]), "r"(b[1]));
}

// ---------------- kernel 0: detect label width ----------------
__global__ void detect_labels_kernel(const unsigned int* __restrict__ w) {
    __shared__ int any;
    if (threadIdx.x == 0) any = 0;
    __syncthreads();
    for (int i = 1 + 2 * threadIdx.x; i < 2 * N; i += 2 * blockDim.x)
        if (w[i] != 0u) any = 1;
    __syncthreads();
    if (threadIdx.x == 0) g_is64 = (any == 0) ? 1 : 0;
}

// ---------------- kernel 1: row squared norms (fp32 exact) ----------------
__global__ void norms_kernel(const float* __restrict__ feat,
                             const float* __restrict__ feat2) {
    int wid  = (blockIdx.x * blockDim.x + threadIdx.x) >> 5;
    int lane = threadIdx.x & 31;
    if (wid >= N + M) return;
    const float* src = (wid < N) ? feat + (size_t)wid * D : feat2 + (size_t)(wid - N) * D;
    float s = 0.f;
#pragma unroll
    for (int j = 0; j < 4; j++) {
        float4 v = ((const float4*)src)[lane + 32 * j];
        s += v.x * v.x + v.y * v.y + v.z * v.z + v.w * v.w;
    }
#pragma unroll
    for (int off = 16; off; off >>= 1) s += __shfl_xor_sync(0xffffffffu, s, off);
    if (lane == 0) { if (wid < N) g_x2[wid] = s; else g_y2[wid - N] = s; }
}

// ---------------- kernel 2: fp32 -> tf32 (round-to-nearest) ----------------
__global__ void convert_kernel(const float* __restrict__ feat,
                               const float* __restrict__ feat2) {
    int i = blockIdx.x * blockDim.x + threadIdx.x;
    int stride = gridDim.x * blockDim.x;
    for (int q = i; q < (N * D) / 4; q += stride) {
        float4 v = ((const float4*)feat)[q];
        uint4 o = { to_tf32(v.x), to_tf32(v.y), to_tf32(v.z), to_tf32(v.w) };
        ((uint4*)g_at)[q] = o;
    }
    for (int q = i; q < (M * D) / 4; q += stride) {
        float4 v = ((const float4*)feat2)[q];
        uint4 o = { to_tf32(v.x), to_tf32(v.y), to_tf32(v.z), to_tf32(v.w) };
        ((uint4*)g_bt)[q] = o;
    }
}

// ---------------- kernel 3: tf32 mma GEMM + fused softmax epilogue ----------------
__device__ __forceinline__ void load_stage(int it, int r0, int c0, char* dyn, int tid) {
    const int st  = it & (NSTG - 1);
    const int kc0 = it * KC;
    char* A = dyn + st * STAGE_BYTES;
    char* B = A + BT * STRD * 4;
#pragma unroll
    for (int i = 0; i < 2; i++) {       // A: 128 rows x 4 groups of 4 floats
        int q = tid + 256 * i;
        int row = q >> 2, g = q & 3;
        cp16(A + (row * STRD + g * 4) * 4, &g_at[(size_t)(r0 + row) * D + kc0 + g * 4]);
    }
#pragma unroll
    for (int i = 0; i < 2; i++) {       // B: 128 cols x 4 groups
        int q = tid + 256 * i;
        int col = q >> 2, g = q & 3;
        cp16(B + (col * STRD + g * 4) * 4, &g_bt[(size_t)(c0 + col) * D + kc0 + g * 4]);
    }
}

__global__ __launch_bounds__(256, 2)
void gemm_kernel(const void* __restrict__ labels,
                 const float* __restrict__ temp) {
    extern __shared__ char dyn[];
    __shared__ float x2s[BT], y2s[BT];
    __shared__ int   lbs[BT];
    __shared__ float rowsum[BT][4];

    const int tid  = threadIdx.x;
    const int wid  = tid >> 5;
    const int lane = tid & 31;
    const int wm   = wid & 1;        // 2 row groups of 64
    const int wn   = wid >> 1;       // 4 col groups of 32
    const int g    = lane >> 2;      // 0..7
    const int t    = lane & 3;       // 0..3
    const int r0   = blockIdx.y * BT;
    const int c0   = blockIdx.x * BT;

    if (tid < BT) {
        x2s[tid] = g_x2[r0 + tid];
        y2s[tid] = g_y2[c0 + tid];
        long long l = g_is64 ? ((const long long*)labels)[r0 + tid]
                             : (long long)((const int*)labels)[r0 + tid];
        if (l < 0) l = 0; if (l >= M) l = M - 1;
        lbs[tid] = (int)l;
    }

    float c[4][4][4];
#pragma unroll
    for (int mt = 0; mt < 4; mt++)
#pragma unroll
        for (int nt = 0; nt < 4; nt++)
#pragma unroll
            for (int j = 0; j < 4; j++) c[mt][nt][j] = 0.f;

    // prologue
    for (int p = 0; p < NSTG - 1; p++) { load_stage(p, r0, c0, dyn, tid); cp_commit(); }

    for (int it = 0; it < ITERS; ++it) {
        cp_wait2();
        __syncthreads();
        const int st = it & (NSTG - 1);
        const uint32_t* As = (const uint32_t*)(dyn + st * STAGE_BYTES);
        const uint32_t* Bs = As + BT * STRD;
#pragma unroll
        for (int s = 0; s < 2; s++) {
            const int k0 = s * 8;
            uint32_t af[4][4];
#pragma unroll
            for (int mt = 0; mt < 4; mt++) {
                int r = wm * 64 + mt * 16 + g;
                af[mt][0] = As[r * STRD + k0 + t];
                af[mt][1] = As[(r + 8) * STRD + k0 + t];
                af[mt][2] = As[r * STRD + k0 + t + 4];
                af[mt][3] = As[(r + 8) * STRD + k0 + t + 4];
            }
            uint32_t bf[4][2];
#pragma unroll
            for (int nt = 0; nt < 4; nt++) {
                int cc = wn * 32 + nt * 8 + g;
                bf[nt][0] = Bs[cc * STRD + k0 + t];
                bf[nt][1] = Bs[cc * STRD + k0 + t + 4];
            }
#pragma unroll
            for (int mt = 0; mt < 4; mt++)
#pragma unroll
                for (int nt = 0; nt < 4; nt++) mma8(c[mt][nt], af[mt], bf[nt]);
        }
        if (it + NSTG - 1 < ITERS) load_stage(it + NSTG - 1, r0, c0, dyn, tid);
        cp_commit();
    }
    __syncthreads();

    // ---- fused epilogue ----
    const float invT = 1.0f / temp[0];
    const float cexp = -invT * 1.4426950408889634f;  // -log2(e)/T

    float esum[4][2];
#pragma unroll
    for (int mt = 0; mt < 4; mt++) { esum[mt][0] = 0.f; esum[mt][1] = 0.f; }

#pragma unroll
    for (int mt = 0; mt < 4; mt++) {
        const int rlo = wm * 64 + mt * 16 + g;
        const int rhi = rlo + 8;
        const float xlo = x2s[rlo], xhi = x2s[rhi];
        const int llo = lbs[rlo], lhi = lbs[rhi];
#pragma unroll
        for (int nt = 0; nt < 4; nt++) {
            const int cl = wn * 32 + nt * 8 + t * 2;
            const float y0 = y2s[cl], y1 = y2s[cl + 1];
            const int cg0 = c0 + cl, cg1 = cg0 + 1;
            float d, dist;
            d = fmaxf(xlo + y0 - 2.0f * c[mt][nt][0], 0.f); dist = sqa(d);
            esum[mt][0] += ex2a(dist * cexp); if (cg0 == llo) g_dlbl[r0 + rlo] = dist;
            d = fmaxf(xlo + y1 - 2.0f * c[mt][nt][1], 0.f); dist = sqa(d);
            esum[mt][0] += ex2a(dist * cexp); if (cg1 == llo) g_dlbl[r0 + rlo] = dist;
            d = fmaxf(xhi + y0 - 2.0f * c[mt][nt][2], 0.f); dist = sqa(d);
            esum[mt][1] += ex2a(dist * cexp); if (cg0 == lhi) g_dlbl[r0 + rhi] = dist;
            d = fmaxf(xhi + y1 - 2.0f * c[mt][nt][3], 0.f); dist = sqa(d);
            esum[mt][1] += ex2a(dist * cexp); if (cg1 == lhi) g_dlbl[r0 + rhi] = dist;
        }
    }

    // quad reduce (lanes t=0..3 share the same rows)
#pragma unroll
    for (int mt = 0; mt < 4; mt++)
#pragma unroll
        for (int h = 0; h < 2; h++) {
            float v = esum[mt][h];
            v += __shfl_xor_sync(0xffffffffu, v, 1);
            v += __shfl_xor_sync(0xffffffffu, v, 2);
            esum[mt][h] = v;
        }
    if (t == 0) {
#pragma unroll
        for (int mt = 0; mt < 4; mt++) {
            rowsum[wm * 64 + mt * 16 + g][wn]     = esum[mt][0];
            rowsum[wm * 64 + mt * 16 + g + 8][wn] = esum[mt][1];
        }
    }
    __syncthreads();
    if (tid < BT) {
        float s = ((rowsum[tid][0] + rowsum[tid][1]) + rowsum[tid][2]) + rowsum[tid][3];
        g_part[blockIdx.x][r0 + tid] = s;
    }
}

// ---------------- finalize: fixed-order partial combine ----------------
__global__ void finalize_kernel(const float* __restrict__ temp) {
    int row = blockIdx.x * blockDim.x + threadIdx.x;
    if (row >= N) return;
    float s = 0.f;
#pragma unroll
    for (int cidx = 0; cidx < M / BT; cidx++) s += g_part[cidx][row];
    float invT = 1.0f / temp[0];
    g_nll[row] = g_dlbl[row] * invT + __logf(s);
}

// ---------------- mean reduction ----------------
__global__ void reduce_kernel(float* __restrict__ out) {
    __shared__ float sh[256];
    int tid = threadIdx.x;
    float s = 0.f;
    for (int i = tid; i < N; i += 256) s += g_nll[i];
    sh[tid] = s;
    __syncthreads();
    for (int off = 128; off; off >>= 1) {
        if (tid < off) sh[tid] += sh[tid + off];
        __syncthreads();
    }
    if (tid == 0) out[0] = sh[0] / (float)N;
}

// ---------------- launch ----------------
extern "C" void kernel_launch(void* const* d_in, const int* in_sizes, int n_in,
                              void* d_out, int out_size) {
    const float* feat   = (const float*)d_in[0];
    const float* feat2  = (const float*)d_in[1];
    const void*  labels = d_in[2];
    const float* temp   = (const float*)d_in[3];
    float* out = (float*)d_out;

    static int attr_done = 0;
    if (!attr_done) {
        cudaFuncSetAttribute(gemm_kernel, cudaFuncAttributeMaxDynamicSharedMemorySize, SMEM_DYN);
        attr_done = 1;
    }

    detect_labels_kernel<<<1, 256>>>((const unsigned int*)labels);
    norms_kernel<<<(N + M) / 8, 256>>>(feat, feat2);
    convert_kernel<<<1024, 256>>>(feat, feat2);
    dim3 grid(M / BT, N / BT);
    gemm_kernel<<<grid, 256, SMEM_DYN>>>(labels, temp);
    finalize_kernel<<<N / 256, 256>>>(temp);
    reduce_kernel<<<1, 256>>>(out);
}

// round 6
// speedup vs baseline: 10.4749x; 1.7456x over previous
#include <cuda_runtime.h>
#include <cuda_fp16.h>
#include <math.h>
#include <stdint.h>

#define N 4096
#define M 4096
#define D 512

#define BT 128          // CTA tile (rows and cols)
#define KC 32           // K per pipeline stage
#define NSTG 4
#define ITERS (D / KC)  // 16
#define ROWB 80         // smem row stride in bytes (40 halfs) - conflict-free for ldmatrix
#define STAGE_BYTES (2 * BT * ROWB)     // 20480 (A 10240 + B 10240)
#define SMEM_DYN (NSTG * STAGE_BYTES)   // 81920

typedef unsigned long long u64;

// scratch
__device__ __align__(16) __half g_ah[N * D];   // feat  in fp16
__device__ __align__(16) __half g_bh[M * D];   // feat2 in fp16
__device__ __align__(16) float g_x2[N];
__device__ __align__(16) float g_y2[M];
__device__ __align__(16) float g_part[M / BT][N];
__device__ __align__(16) float g_dlbl[N];
__device__ __align__(16) float g_nll[N];
__device__ int g_is64;

// ---------------- helpers ----------------
__device__ __forceinline__ uint32_t smem_u32(const void* p) {
    uint32_t a;
    asm("{ .reg .u64 t; cvta.to.shared.u64 t, %1; cvt.u32.u64 %0, t; }" : "=r"(a) : "l"(p));
    return a;
}
__device__ __forceinline__ void cp16(uint32_t dst, const void* src) {
    asm volatile("cp.async.cg.shared.global [%0], [%1], 16;" :: "r"(dst), "l"(src) : "memory");
}
__device__ __forceinline__ void cp_commit() { asm volatile("cp.async.commit_group;" ::: "memory"); }
__device__ __forceinline__ void cp_wait2()  { asm volatile("cp.async.wait_group 2;"  ::: "memory"); }
__device__ __forceinline__ float sqa(float x)  { float r; asm("sqrt.approx.f32 %0, %1;" : "=f"(r) : "f"(x)); return r; }
__device__ __forceinline__ float ex2a(float x) { float r; asm("ex2.approx.f32 %0, %1;"  : "=f"(r) : "f"(x)); return r; }

__device__ __forceinline__ void ldmx4(uint32_t* r, uint32_t a) {
    asm volatile("ldmatrix.sync.aligned.m8n8.x4.shared.b16 {%0,%1,%2,%3}, [%4];"
                 : "=r"(r[0]), "=r"(r[1]), "=r"(r[2]), "=r"(r[3]) : "r"(a));
}
__device__ __forceinline__ void ldmx2(uint32_t* r, uint32_t a) {
    asm volatile("ldmatrix.sync.aligned.m8n8.x2.shared.b16 {%0,%1}, [%2];"
                 : "=r"(r[0]), "=r"(r[1]) : "r"(a));
}
__device__ __forceinline__ void mma16(float* c, const uint32_t* a, const uint32_t* b) {
    asm volatile(
        "mma.sync.aligned.m16n8k16.row.col.f32.f16.f16.f32 "
        "{%0,%1,%2,%3}, {%4,%5,%6,%7}, {%8,%9}, {%0,%1,%2,%3};"
        : "+f"(c[0]), "+f"(c[1]), "+f"(c[2]), "+f"(c[3])
        : "r"(a[0]), "r"(a[1]), "r"(a[2]), "r"(a[3]), "r"(b[0]), "r"(b[1]));
}

// ---------------- kernel 0: detect label width ----------------
__global__ void detect_labels_kernel(const unsigned int* __restrict__ w) {
    __shared__ int any;
    if (threadIdx.x == 0) any = 0;
    __syncthreads();
    for (int i = 1 + 2 * threadIdx.x; i < 2 * N; i += 2 * blockDim.x)
        if (w[i] != 0u) any = 1;
    __syncthreads();
    if (threadIdx.x == 0) g_is64 = (any == 0) ? 1 : 0;
}

// ---------------- kernel 1: row squared norms (fp32 exact) ----------------
__global__ void norms_kernel(const float* __restrict__ feat,
                             const float* __restrict__ feat2) {
    int wid  = (blockIdx.x * blockDim.x + threadIdx.x) >> 5;
    int lane = threadIdx.x & 31;
    if (wid >= N + M) return;
    const float* src = (wid < N) ? feat + (size_t)wid * D : feat2 + (size_t)(wid - N) * D;
    float s = 0.f;
#pragma unroll
    for (int j = 0; j < 4; j++) {
        float4 v = ((const float4*)src)[lane + 32 * j];
        s += v.x * v.x + v.y * v.y + v.z * v.z + v.w * v.w;
    }
#pragma unroll
    for (int off = 16; off; off >>= 1) s += __shfl_xor_sync(0xffffffffu, s, off);
    if (lane == 0) { if (wid < N) g_x2[wid] = s; else g_y2[wid - N] = s; }
}

// ---------------- kernel 2: fp32 -> fp16 ----------------
__global__ void convert_kernel(const float* __restrict__ feat,
                               const float* __restrict__ feat2) {
    int i = blockIdx.x * blockDim.x + threadIdx.x;
    int stride = gridDim.x * blockDim.x;
    for (int q = i; q < (N * D) / 4; q += stride) {
        float4 v = ((const float4*)feat)[q];
        __half2 h0 = __floats2half2_rn(v.x, v.y);
        __half2 h1 = __floats2half2_rn(v.z, v.w);
        uint2 o = { *(uint32_t*)&h0, *(uint32_t*)&h1 };
        ((uint2*)g_ah)[q] = o;
    }
    for (int q = i; q < (M * D) / 4; q += stride) {
        float4 v = ((const float4*)feat2)[q];
        __half2 h0 = __floats2half2_rn(v.x, v.y);
        __half2 h1 = __floats2half2_rn(v.z, v.w);
        uint2 o = { *(uint32_t*)&h0, *(uint32_t*)&h1 };
        ((uint2*)g_bh)[q] = o;
    }
}

// ---------------- kernel 3: fp16 mma GEMM + fused softmax epilogue ----------------
__device__ __forceinline__ void load_stage(int it, int r0, int c0, uint32_t sb, int tid) {
    const int st  = it & (NSTG - 1);
    const int kc0 = it * KC;
    const uint32_t A = sb + st * STAGE_BYTES;
    const uint32_t B = A + BT * ROWB;
#pragma unroll
    for (int i = 0; i < 2; i++) {       // A: 128 rows x 4 chunks of 8 halfs (16B)
        int q = tid + 256 * i;
        int row = q >> 2, g = q & 3;
        cp16(A + row * ROWB + g * 16, &g_ah[(size_t)(r0 + row) * D + kc0 + g * 8]);
    }
#pragma unroll
    for (int i = 0; i < 2; i++) {       // B: 128 cols x 4 chunks
        int q = tid + 256 * i;
        int col = q >> 2, g = q & 3;
        cp16(B + col * ROWB + g * 16, &g_bh[(size_t)(c0 + col) * D + kc0 + g * 8]);
    }
}

__global__ __launch_bounds__(256, 2)
void gemm_kernel(const void* __restrict__ labels,
                 const float* __restrict__ temp) {
    extern __shared__ char dyn[];
    __shared__ float x2s[BT], y2s[BT];
    __shared__ int   lbs[BT];
    __shared__ float rowsum[BT][4];

    const uint32_t sb = smem_u32(dyn);
    const int tid  = threadIdx.x;
    const int wid  = tid >> 5;
    const int lane = tid & 31;
    const int wm   = wid & 1;        // 2 row groups of 64
    const int wn   = wid >> 1;       // 4 col groups of 32
    const int g    = lane >> 2;      // 0..7
    const int t    = lane & 3;       // 0..3
    const int r0   = blockIdx.y * BT;
    const int c0   = blockIdx.x * BT;

    if (tid < BT) {
        x2s[tid] = g_x2[r0 + tid];
        y2s[tid] = g_y2[c0 + tid];
        long long l = g_is64 ? ((const long long*)labels)[r0 + tid]
                             : (long long)((const int*)labels)[r0 + tid];
        if (l < 0) l = 0; if (l >= M) l = M - 1;
        lbs[tid] = (int)l;
    }

    // ldmatrix per-lane base offsets (within a stage)
    const uint32_t aoff = (uint32_t)((wm * 64 + (lane & 15)) * ROWB + ((lane >> 4) * 16));
    const uint32_t boff = (uint32_t)(BT * ROWB + (wn * 32 + (lane & 7)) * ROWB + (((lane >> 3) & 1) * 16));

    float c[4][4][4];
#pragma unroll
    for (int mt = 0; mt < 4; mt++)
#pragma unroll
        for (int nt = 0; nt < 4; nt++)
#pragma unroll
            for (int j = 0; j < 4; j++) c[mt][nt][j] = 0.f;

    // prologue
    for (int p = 0; p < NSTG - 1; p++) { load_stage(p, r0, c0, sb, tid); cp_commit(); }

    for (int it = 0; it < ITERS; ++it) {
        cp_wait2();
        __syncthreads();
        const uint32_t stg = sb + (it & (NSTG - 1)) * STAGE_BYTES;
#pragma unroll
        for (int s = 0; s < 2; s++) {
            const uint32_t ks = s * 32;     // 16 halfs = 32 bytes
            uint32_t af[4][4];
#pragma unroll
            for (int mt = 0; mt < 4; mt++) ldmx4(af[mt], stg + aoff + mt * (16 * ROWB) + ks);
            uint32_t bf[4][2];
#pragma unroll
            for (int nt = 0; nt < 4; nt++) ldmx2(bf[nt], stg + boff + nt * (8 * ROWB) + ks);
#pragma unroll
            for (int mt = 0; mt < 4; mt++)
#pragma unroll
                for (int nt = 0; nt < 4; nt++) mma16(c[mt][nt], af[mt], bf[nt]);
        }
        if (it + NSTG - 1 < ITERS) load_stage(it + NSTG - 1, r0, c0, sb, tid);
        cp_commit();
    }
    __syncthreads();

    // ---- fused epilogue ----
    const float invT = 1.0f / temp[0];
    const float cexp = -invT * 1.4426950408889634f;  // -log2(e)/T

    float esum[4][2];
#pragma unroll
    for (int mt = 0; mt < 4; mt++) { esum[mt][0] = 0.f; esum[mt][1] = 0.f; }

#pragma unroll
    for (int mt = 0; mt < 4; mt++) {
        const int rlo = wm * 64 + mt * 16 + g;
        const int rhi = rlo + 8;
        const float xlo = x2s[rlo], xhi = x2s[rhi];
        const int llo = lbs[rlo], lhi = lbs[rhi];
#pragma unroll
        for (int nt = 0; nt < 4; nt++) {
            const int cl = wn * 32 + nt * 8 + t * 2;
            const float y0 = y2s[cl], y1 = y2s[cl + 1];
            const int cg0 = c0 + cl, cg1 = cg0 + 1;
            float d, dist;
            d = fmaxf(xlo + y0 - 2.0f * c[mt][nt][0], 0.f); dist = sqa(d);
            esum[mt][0] += ex2a(dist * cexp); if (cg0 == llo) g_dlbl[r0 + rlo] = dist;
            d = fmaxf(xlo + y1 - 2.0f * c[mt][nt][1], 0.f); dist = sqa(d);
            esum[mt][0] += ex2a(dist * cexp); if (cg1 == llo) g_dlbl[r0 + rlo] = dist;
            d = fmaxf(xhi + y0 - 2.0f * c[mt][nt][2], 0.f); dist = sqa(d);
            esum[mt][1] += ex2a(dist * cexp); if (cg0 == lhi) g_dlbl[r0 + rhi] = dist;
            d = fmaxf(xhi + y1 - 2.0f * c[mt][nt][3], 0.f); dist = sqa(d);
            esum[mt][1] += ex2a(dist * cexp); if (cg1 == lhi) g_dlbl[r0 + rhi] = dist;
        }
    }

    // quad reduce (lanes t=0..3 share the same rows)
#pragma unroll
    for (int mt = 0; mt < 4; mt++)
#pragma unroll
        for (int h = 0; h < 2; h++) {
            float v = esum[mt][h];
            v += __shfl_xor_sync(0xffffffffu, v, 1);
            v += __shfl_xor_sync(0xffffffffu, v, 2);
            esum[mt][h] = v;
        }
    if (t == 0) {
#pragma unroll
        for (int mt = 0; mt < 4; mt++) {
            rowsum[wm * 64 + mt * 16 + g][wn]     = esum[mt][0];
            rowsum[wm * 64 + mt * 16 + g + 8][wn] = esum[mt][1];
        }
    }
    __syncthreads();
    if (tid < BT) {
        float s = ((rowsum[tid][0] + rowsum[tid][1]) + rowsum[tid][2]) + rowsum[tid][3];
        g_part[blockIdx.x][r0 + tid] = s;
    }
}

// ---------------- finalize: fixed-order partial combine ----------------
__global__ void finalize_kernel(const float* __restrict__ temp) {
    int row = blockIdx.x * blockDim.x + threadIdx.x;
    if (row >= N) return;
    float s = 0.f;
#pragma unroll
    for (int cidx = 0; cidx < M / BT; cidx++) s += g_part[cidx][row];
    float invT = 1.0f / temp[0];
    g_nll[row] = g_dlbl[row] * invT + __logf(s);
}

// ---------------- mean reduction ----------------
__global__ void reduce_kernel(float* __restrict__ out) {
    __shared__ float sh[256];
    int tid = threadIdx.x;
    float s = 0.f;
    for (int i = tid; i < N; i += 256) s += g_nll[i];
    sh[tid] = s;
    __syncthreads();
    for (int off = 128; off; off >>= 1) {
        if (tid < off) sh[tid] += sh[tid + off];
        __syncthreads();
    }
    if (tid == 0) out[0] = sh[0] / (float)N;
}

// ---------------- launch ----------------
extern "C" void kernel_launch(void* const* d_in, const int* in_sizes, int n_in,
                              void* d_out, int out_size) {
    const float* feat   = (const float*)d_in[0];
    const float* feat2  = (const float*)d_in[1];
    const void*  labels = d_in[2];
    const float* temp   = (const float*)d_in[3];
    float* out = (float*)d_out;

    static int attr_done = 0;
    if (!attr_done) {
        cudaFuncSetAttribute(gemm_kernel, cudaFuncAttributeMaxDynamicSharedMemorySize, SMEM_DYN);
        attr_done = 1;
    }

    detect_labels_kernel<<<1, 256>>>((const unsigned int*)labels);
    norms_kernel<<<(N + M) / 8, 256>>>(feat, feat2);
    convert_kernel<<<1024, 256>>>(feat, feat2);
    dim3 grid(M / BT, N / BT);
    gemm_kernel<<<grid, 256, SMEM_DYN>>>(labels, temp);
    finalize_kernel<<<N / 256, 256>>>(temp);
    reduce_kernel<<<1, 256>>>(out);
}

// round 7
// speedup vs baseline: 15.9327x; 1.5210x over previous
#include <cuda_runtime.h>
#include <cuda_fp16.h>
#include <math.h>
#include <stdint.h>

#define N 4096
#define M 4096
#define D 512

#define BT 128          // CTA tile (rows and cols)
#define KC 64           // K (int8 bytes) per pipeline stage
#define NSTG 4
#define ITERS (D / KC)  // 8
#define ROWB 80         // smem row stride in bytes (64B data + 16B pad, ldmatrix conflict-free)
#define STAGE_BYTES (2 * BT * ROWB)     // 20480
#define SMEM_DYN (NSTG * STAGE_BYTES)   // 81920

typedef unsigned long long u64;

// scratch
__device__ __align__(16) int8_t g_ai8[N * D];   // feat  quantized
__device__ __align__(16) int8_t g_bi8[M * D];   // feat2 quantized
__device__ __align__(16) float g_sa[N];         // per-row scale (amax/127)
__device__ __align__(16) float g_sb[M];
__device__ __align__(16) float g_x2[N];
__device__ __align__(16) float g_y2[M];
__device__ __align__(16) float g_part[M / BT][N];
__device__ __align__(16) float g_dlbl[N];
__device__ __align__(16) float g_nll[N];
__device__ int g_is64;

// ---------------- helpers ----------------
__device__ __forceinline__ uint32_t smem_u32(const void* p) {
    uint32_t a;
    asm("{ .reg .u64 t; cvta.to.shared.u64 t, %1; cvt.u32.u64 %0, t; }" : "=r"(a) : "l"(p));
    return a;
}
__device__ __forceinline__ void cp16(uint32_t dst, const void* src) {
    asm volatile("cp.async.cg.shared.global [%0], [%1], 16;" :: "r"(dst), "l"(src) : "memory");
}
__device__ __forceinline__ void cp_commit() { asm volatile("cp.async.commit_group;" ::: "memory"); }
__device__ __forceinline__ void cp_wait2()  { asm volatile("cp.async.wait_group 2;"  ::: "memory"); }
__device__ __forceinline__ float sqa(float x)  { float r; asm("sqrt.approx.f32 %0, %1;" : "=f"(r) : "f"(x)); return r; }
__device__ __forceinline__ float ex2a(float x) { float r; asm("ex2.approx.f32 %0, %1;"  : "=f"(r) : "f"(x)); return r; }

__device__ __forceinline__ void ldmx4(uint32_t* r, uint32_t a) {
    asm volatile("ldmatrix.sync.aligned.m8n8.x4.shared.b16 {%0,%1,%2,%3}, [%4];"
                 : "=r"(r[0]), "=r"(r[1]), "=r"(r[2]), "=r"(r[3]) : "r"(a));
}
__device__ __forceinline__ void ldmx2(uint32_t* r, uint32_t a) {
    asm volatile("ldmatrix.sync.aligned.m8n8.x2.shared.b16 {%0,%1}, [%2];"
                 : "=r"(r[0]), "=r"(r[1]) : "r"(a));
}
// s8 IMMA: 16x8x32, s32 accum. Byte layout of fragments == fp16 m16n8k16 layout.
__device__ __forceinline__ void mma32(int* c, const uint32_t* a, const uint32_t* b) {
    asm volatile(
        "mma.sync.aligned.m16n8k32.row.col.s32.s8.s8.s32 "
        "{%0,%1,%2,%3}, {%4,%5,%6,%7}, {%8,%9}, {%0,%1,%2,%3};"
        : "+r"(c[0]), "+r"(c[1]), "+r"(c[2]), "+r"(c[3])
        : "r"(a[0]), "r"(a[1]), "r"(a[2]), "r"(a[3]), "r"(b[0]), "r"(b[1]));
}

// ---------------- kernel 0: detect label width ----------------
__global__ void detect_labels_kernel(const unsigned int* __restrict__ w) {
    __shared__ int any;
    if (threadIdx.x == 0) any = 0;
    __syncthreads();
    for (int i = 1 + 2 * threadIdx.x; i < 2 * N; i += 2 * blockDim.x)
        if (w[i] != 0u) any = 1;
    __syncthreads();
    if (threadIdx.x == 0) g_is64 = (any == 0) ? 1 : 0;
}

// ---------------- kernel 1: fused norms + per-row int8 quantization ----------------
// one warp per row: computes ||x||^2 (fp32 exact), amax, then writes 512 int8.
__global__ void quant_kernel(const float* __restrict__ feat,
                             const float* __restrict__ feat2) {
    int wid  = (blockIdx.x * blockDim.x + threadIdx.x) >> 5;
    int lane = threadIdx.x & 31;
    if (wid >= N + M) return;
    const int isA = (wid < N);
    const int row = isA ? wid : wid - N;
    const float* src = isA ? feat + (size_t)row * D : feat2 + (size_t)row * D;

    float4 v[4];
#pragma unroll
    for (int j = 0; j < 4; j++) v[j] = ((const float4*)src)[lane * 4 + j];

    float ss = 0.f, am = 0.f;
#pragma unroll
    for (int j = 0; j < 4; j++) {
        ss += v[j].x * v[j].x + v[j].y * v[j].y + v[j].z * v[j].z + v[j].w * v[j].w;
        am = fmaxf(am, fmaxf(fmaxf(fabsf(v[j].x), fabsf(v[j].y)),
                             fmaxf(fabsf(v[j].z), fabsf(v[j].w))));
    }
#pragma unroll
    for (int off = 16; off; off >>= 1) {
        ss += __shfl_xor_sync(0xffffffffu, ss, off);
        am = fmaxf(am, __shfl_xor_sync(0xffffffffu, am, off));
    }
    const float inv = (am > 0.f) ? (127.0f / am) : 0.f;

    uint32_t words[4];
#pragma unroll
    for (int j = 0; j < 4; j++) {
        int q0 = __float2int_rn(v[j].x * inv);
        int q1 = __float2int_rn(v[j].y * inv);
        int q2 = __float2int_rn(v[j].z * inv);
        int q3 = __float2int_rn(v[j].w * inv);
        q0 = max(-127, min(127, q0)); q1 = max(-127, min(127, q1));
        q2 = max(-127, min(127, q2)); q3 = max(-127, min(127, q3));
        words[j] = (uint32_t)(q0 & 0xFF) | ((uint32_t)(q1 & 0xFF) << 8)
                 | ((uint32_t)(q2 & 0xFF) << 16) | ((uint32_t)(q3 & 0xFF) << 24);
    }
    int8_t* dst = (isA ? g_ai8 : g_bi8) + (size_t)row * D;
    ((uint4*)dst)[lane] = make_uint4(words[0], words[1], words[2], words[3]);

    if (lane == 0) {
        const float sc = am * (1.0f / 127.0f);
        if (isA) { g_x2[row] = ss; g_sa[row] = sc; }
        else     { g_y2[row] = ss; g_sb[row] = sc; }
    }
}

// ---------------- kernel 2: int8 mma GEMM + fused softmax epilogue ----------------
__device__ __forceinline__ void load_stage(int it, int r0, int c0, uint32_t sb, int tid) {
    const int st  = it & (NSTG - 1);
    const int kc0 = it * KC;                  // byte offset in row
    const uint32_t A = sb + st * STAGE_BYTES;
    const uint32_t B = A + BT * ROWB;
#pragma unroll
    for (int i = 0; i < 2; i++) {       // A: 128 rows x 4 chunks of 16B
        int q = tid + 256 * i;
        int row = q >> 2, g = q & 3;
        cp16(A + row * ROWB + g * 16, &g_ai8[(size_t)(r0 + row) * D + kc0 + g * 16]);
    }
#pragma unroll
    for (int i = 0; i < 2; i++) {       // B: 128 cols x 4 chunks
        int q = tid + 256 * i;
        int col = q >> 2, g = q & 3;
        cp16(B + col * ROWB + g * 16, &g_bi8[(size_t)(c0 + col) * D + kc0 + g * 16]);
    }
}

__global__ __launch_bounds__(256, 2)
void gemm_kernel(const void* __restrict__ labels,
                 const float* __restrict__ temp) {
    extern __shared__ char dyn[];
    __shared__ float x2s[BT], y2s[BT], sas[BT], sbs[BT];
    __shared__ int   lbs[BT];
    __shared__ float rowsum[BT][4];

    const uint32_t sb = smem_u32(dyn);
    const int tid  = threadIdx.x;
    const int wid  = tid >> 5;
    const int lane = tid & 31;
    const int wm   = wid & 1;        // 2 row groups of 64
    const int wn   = wid >> 1;       // 4 col groups of 32
    const int g    = lane >> 2;      // 0..7
    const int t    = lane & 3;       // 0..3
    const int r0   = blockIdx.y * BT;
    const int c0   = blockIdx.x * BT;

    if (tid < BT) {
        x2s[tid] = g_x2[r0 + tid];
        y2s[tid] = g_y2[c0 + tid];
        sas[tid] = g_sa[r0 + tid];
        sbs[tid] = g_sb[c0 + tid];
        long long l = g_is64 ? ((const long long*)labels)[r0 + tid]
                             : (long long)((const int*)labels)[r0 + tid];
        if (l < 0) l = 0; if (l >= M) l = M - 1;
        lbs[tid] = (int)l;
    }

    // ldmatrix per-lane base offsets (within a stage); byte layout identical to fp16 case
    const uint32_t aoff = (uint32_t)((wm * 64 + (lane & 15)) * ROWB + ((lane >> 4) * 16));
    const uint32_t boff = (uint32_t)(BT * ROWB + (wn * 32 + (lane & 7)) * ROWB + (((lane >> 3) & 1) * 16));

    int c[4][4][4];
#pragma unroll
    for (int mt = 0; mt < 4; mt++)
#pragma unroll
        for (int nt = 0; nt < 4; nt++)
#pragma unroll
            for (int j = 0; j < 4; j++) c[mt][nt][j] = 0;

    // prologue
    for (int p = 0; p < NSTG - 1; p++) { load_stage(p, r0, c0, sb, tid); cp_commit(); }

    for (int it = 0; it < ITERS; ++it) {
        cp_wait2();
        __syncthreads();
        const uint32_t stg = sb + (it & (NSTG - 1)) * STAGE_BYTES;
#pragma unroll
        for (int s = 0; s < 2; s++) {
            const uint32_t ks = s * 32;     // 32 bytes = one k32 step
            uint32_t af[4][4];
#pragma unroll
            for (int mt = 0; mt < 4; mt++) ldmx4(af[mt], stg + aoff + mt * (16 * ROWB) + ks);
            uint32_t bf[4][2];
#pragma unroll
            for (int nt = 0; nt < 4; nt++) ldmx2(bf[nt], stg + boff + nt * (8 * ROWB) + ks);
#pragma unroll
            for (int mt = 0; mt < 4; mt++)
#pragma unroll
                for (int nt = 0; nt < 4; nt++) mma32(c[mt][nt], af[mt], bf[nt]);
        }
        if (it + NSTG - 1 < ITERS) load_stage(it + NSTG - 1, r0, c0, sb, tid);
        cp_commit();
    }
    __syncthreads();

    // ---- fused epilogue ----
    const float invT = 1.0f / temp[0];
    const float cexp = -invT * 1.4426950408889634f;  // -log2(e)/T

    float esum[4][2];
#pragma unroll
    for (int mt = 0; mt < 4; mt++) { esum[mt][0] = 0.f; esum[mt][1] = 0.f; }

#pragma unroll
    for (int mt = 0; mt < 4; mt++) {
        const int rlo = wm * 64 + mt * 16 + g;
        const int rhi = rlo + 8;
        const float xlo = x2s[rlo], xhi = x2s[rhi];
        const float slo = sas[rlo], shi = sas[rhi];
        const int llo = lbs[rlo], lhi = lbs[rhi];
#pragma unroll
        for (int nt = 0; nt < 4; nt++) {
            const int cl = wn * 32 + nt * 8 + t * 2;
            const float y0 = y2s[cl], y1 = y2s[cl + 1];
            const float sc00 = slo * sbs[cl], sc01 = slo * sbs[cl + 1];
            const float sc10 = shi * sbs[cl], sc11 = shi * sbs[cl + 1];
            const int cg0 = c0 + cl, cg1 = cg0 + 1;
            float d, dist;
            d = fmaxf(xlo + y0 - 2.0f * sc00 * (float)c[mt][nt][0], 0.f); dist = sqa(d);
            esum[mt][0] += ex2a(dist * cexp); if (cg0 == llo) g_dlbl[r0 + rlo] = dist;
            d = fmaxf(xlo + y1 - 2.0f * sc01 * (float)c[mt][nt][1], 0.f); dist = sqa(d);
            esum[mt][0] += ex2a(dist * cexp); if (cg1 == llo) g_dlbl[r0 + rlo] = dist;
            d = fmaxf(xhi + y0 - 2.0f * sc10 * (float)c[mt][nt][2], 0.f); dist = sqa(d);
            esum[mt][1] += ex2a(dist * cexp); if (cg0 == lhi) g_dlbl[r0 + rhi] = dist;
            d = fmaxf(xhi + y1 - 2.0f * sc11 * (float)c[mt][nt][3], 0.f); dist = sqa(d);
            esum[mt][1] += ex2a(dist * cexp); if (cg1 == lhi) g_dlbl[r0 + rhi] = dist;
        }
    }

    // quad reduce (lanes t=0..3 share the same rows)
#pragma unroll
    for (int mt = 0; mt < 4; mt++)
#pragma unroll
        for (int h = 0; h < 2; h++) {
            float v = esum[mt][h];
            v += __shfl_xor_sync(0xffffffffu, v, 1);
            v += __shfl_xor_sync(0xffffffffu, v, 2);
            esum[mt][h] = v;
        }
    if (t == 0) {
#pragma unroll
        for (int mt = 0; mt < 4; mt++) {
            rowsum[wm * 64 + mt * 16 + g][wn]     = esum[mt][0];
            rowsum[wm * 64 + mt * 16 + g + 8][wn] = esum[mt][1];
        }
    }
    __syncthreads();
    if (tid < BT) {
        float s = ((rowsum[tid][0] + rowsum[tid][1]) + rowsum[tid][2]) + rowsum[tid][3];
        g_part[blockIdx.x][r0 + tid] = s;
    }
}

// ---------------- finalize: fixed-order partial combine ----------------
__global__ void finalize_kernel(const float* __restrict__ temp) {
    int row = blockIdx.x * blockDim.x + threadIdx.x;
    if (row >= N) return;
    float s = 0.f;
#pragma unroll
    for (int cidx = 0; cidx < M / BT; cidx++) s += g_part[cidx][row];
    float invT = 1.0f / temp[0];
    g_nll[row] = g_dlbl[row] * invT + __logf(s);
}

// ---------------- mean reduction ----------------
__global__ void reduce_kernel(float* __restrict__ out) {
    __shared__ float sh[256];
    int tid = threadIdx.x;
    float s = 0.f;
    for (int i = tid; i < N; i += 256) s += g_nll[i];
    sh[tid] = s;
    __syncthreads();
    for (int off = 128; off; off >>= 1) {
        if (tid < off) sh[tid] += sh[tid + off];
        __syncthreads();
    }
    if (tid == 0) out[0] = sh[0] / (float)N;
}

// ---------------- launch ----------------
extern "C" void kernel_launch(void* const* d_in, const int* in_sizes, int n_in,
                              void* d_out, int out_size) {
    const float* feat   = (const float*)d_in[0];
    const float* feat2  = (const float*)d_in[1];
    const void*  labels = d_in[2];
    const float* temp   = (const float*)d_in[3];
    float* out = (float*)d_out;

    static int attr_done = 0;
    if (!attr_done) {
        cudaFuncSetAttribute(gemm_kernel, cudaFuncAttributeMaxDynamicSharedMemorySize, SMEM_DYN);
        attr_done = 1;
    }

    detect_labels_kernel<<<1, 256>>>((const unsigned int*)labels);
    quant_kernel<<<(N + M) / 8, 256>>>(feat, feat2);
    dim3 grid(M / BT, N / BT);
    gemm_kernel<<<grid, 256, SMEM_DYN>>>(labels, temp);
    finalize_kernel<<<N / 256, 256>>>(temp);
    reduce_kernel<<<1, 256>>>(out);
}